// round 9
// baseline (speedup 1.0000x reference)
#include <cuda_runtime.h>
#include <cuda_bf16.h>
#include <float.h>
#include <math.h>

// Problem constants
#define BB 8
#define LL 200
#define DD 256
#define HH 8
#define HS 32
#define HB 64          // H*B
#define KTOP 20
#define NROW 1600      // B*L
#define LNELEM 409600  // B*L*D

#define CHUNK 16
#define NCHUNK 13      // ceil(200/16)
#define RPAD 260       // row stride in floats (4-float pad; 260*4 % 16 == 0)

// ---------------- device scratch (no allocs allowed) ----------------
__device__ float g_a[NROW * DD];
__device__ float g_b[NROW * DD];
__device__ float g_w[NROW * DD];
__device__ float g_raw[(size_t)HB * LL * LL];
__device__ unsigned int g_selbits[(size_t)HB * LL * 8]; // topk bitmask, 8 words/row
__device__ unsigned char g_mask[LL * LL];

// ---------------- cp.async helpers ----------------
__device__ __forceinline__ void cp16(unsigned int dst, const void* src) {
    asm volatile("cp.async.cg.shared.global [%0], [%1], 16;" :: "r"(dst), "l"(src));
}
__device__ __forceinline__ void cp_commit() {
    asm volatile("cp.async.commit_group;");
}
template <int N>
__device__ __forceinline__ void cp_wait() {
    asm volatile("cp.async.wait_group %0;" :: "n"(N));
}

// ---------------- mask dtype detect + convert ----------------
__global__ void mask_kernel(const void* __restrict__ src) {
    __shared__ int flags[4];
    int t = threadIdx.x;
    if (t < 4) flags[t] = 0;
    __syncthreads();
    const unsigned char* p = (const unsigned char*)src;
    for (int i = t; i < LL * LL; i += 256) {
        if (p[i]) flags[i & 3] = 1;
    }
    __syncthreads();
    int dt;  // 0=u8, 1=i32, 2=f32
    if (flags[1]) dt = 0;
    else if (flags[2] | flags[3]) dt = 2;
    else dt = 1;
    for (int i = t; i < LL * LL; i += 256) {
        unsigned char m;
        if (dt == 0)      m = (p[i] != 0);
        else if (dt == 1) m = (((const int*)src)[i] != 0);
        else              m = (((const float*)src)[i] != 0.0f);
        g_mask[i] = m;
    }
}

// ---------------- zero the selection bitmask ----------------
__global__ void zero_sel_kernel() {
    int i = blockIdx.x * 256 + threadIdx.x;
    if (i < HB * LL * 8) g_selbits[i] = 0u;
}

// ---------------- 3 fused GEMMs: out = X @ W.T + bias ----------------
__global__ void gemm3_kernel(const float* __restrict__ X,
                             const float* __restrict__ W0, const float* __restrict__ B0,
                             const float* __restrict__ W1, const float* __restrict__ B1,
                             const float* __restrict__ W2, const float* __restrict__ B2) {
    const float* W; const float* Bv; float* O;
    if (blockIdx.z == 0)      { W = W0; Bv = B0; O = g_a; }
    else if (blockIdx.z == 1) { W = W1; Bv = B1; O = g_b; }
    else                      { W = W2; Bv = B2; O = g_w; }

    __shared__ float As[16][68];
    __shared__ float Bs[16][68];
    int i0 = blockIdx.y * 64;
    int o0 = blockIdx.x * 64;
    int t = threadIdx.x;
    int tx = t & 15, ty = t >> 4;
    int lr = t >> 2;
    int lc4 = (t & 3) * 4;

    float acc[4][4];
#pragma unroll
    for (int i = 0; i < 4; i++)
#pragma unroll
        for (int j = 0; j < 4; j++) acc[i][j] = 0.f;

    for (int k0 = 0; k0 < DD; k0 += 16) {
        float4 xa = *(const float4*)&X[(size_t)(i0 + lr) * DD + k0 + lc4];
        float4 wb = *(const float4*)&W[(size_t)(o0 + lr) * DD + k0 + lc4];
        As[lc4 + 0][lr] = xa.x; As[lc4 + 1][lr] = xa.y;
        As[lc4 + 2][lr] = xa.z; As[lc4 + 3][lr] = xa.w;
        Bs[lc4 + 0][lr] = wb.x; Bs[lc4 + 1][lr] = wb.y;
        Bs[lc4 + 2][lr] = wb.z; Bs[lc4 + 3][lr] = wb.w;
        __syncthreads();
#pragma unroll
        for (int kk = 0; kk < 16; kk++) {
            float4 a4 = *(const float4*)&As[kk][ty * 4];
            float4 b4 = *(const float4*)&Bs[kk][tx * 4];
            float am[4] = {a4.x, a4.y, a4.z, a4.w};
            float bn[4] = {b4.x, b4.y, b4.z, b4.w};
#pragma unroll
            for (int mi = 0; mi < 4; mi++)
#pragma unroll
                for (int ni = 0; ni < 4; ni++) acc[mi][ni] += am[mi] * bn[ni];
        }
        __syncthreads();
    }
#pragma unroll
    for (int mi = 0; mi < 4; mi++) {
#pragma unroll
        for (int ni = 0; ni < 4; ni++) {
            int oo = o0 + tx * 4 + ni;
            O[(size_t)(i0 + ty * 4 + mi) * DD + oo] = acc[mi][ni] + Bv[oo];
        }
    }
}

// ---------------- Pass 1: tiled + cp.async pipelined + fused top-K -------
// Block = (q, b). ti[b,q,k,:] streamed HBM->smem in 16-row chunks (double
// buffered, cp.async.cg — no registers in the load path). Compute: warp h,
// lane = (half, k): 16-float dot from conflict-free smem + b from L2, then
// a single xor-16 shuffle pair. No other reductions.
__global__ void __launch_bounds__(256, 4) raw_kernel(const float* __restrict__ tm) {
    __shared__ __align__(16) float ti_s[2][CHUNK][RPAD];
    __shared__ float s_row[8][LL];

    int q = blockIdx.x, b = blockIdx.y;
    int t = threadIdx.x, h = t >> 5, lane = t & 31;
    int kl = lane & 15, half = lane >> 4;

    // per-thread A fragment: 16 floats of head h (this thread's half)
    const float* abase = g_a + (size_t)(b * LL + q) * DD + h * HS + half * 16;
    float4 av0 = *(const float4*)(abase + 0);
    float4 av1 = *(const float4*)(abase + 4);
    float4 av2 = *(const float4*)(abase + 8);
    float4 av3 = *(const float4*)(abase + 12);
    float nrm = av0.x*av0.x + av0.y*av0.y + av0.z*av0.z + av0.w*av0.w
              + av1.x*av1.x + av1.y*av1.y + av1.z*av1.z + av1.w*av1.w
              + av2.x*av2.x + av2.y*av2.y + av2.z*av2.z + av2.w*av2.w
              + av3.x*av3.x + av3.y*av3.y + av3.z*av3.z + av3.w*av3.w;
    nrm += __shfl_xor_sync(0xffffffffu, nrm, 16);
    float a2 = sqrtf(nrm);

    const float* tibase = tm + (size_t)(b * LL + q) * LL * DD;
    const float* bbat   = g_b + (size_t)b * LL * DD;
    int hb = h * BB + b;
    size_t rowbase = (size_t)(hb * LL + q) * LL;
    const unsigned char* mrow = g_mask + q * LL;

    // loader mapping: thread t -> row = t>>4 (0..15), 16 consecutive floats
    int lrow = t >> 4;
    int lcol = (t & 15) * 16;
    unsigned int sbase = (unsigned int)__cvta_generic_to_shared(&ti_s[0][0][0]);

    // issue chunk 0
    {
        int gr = min(lrow, LL - 1);
        const float* src = tibase + (size_t)gr * DD + lcol;
        unsigned int dst = sbase + (unsigned int)((lrow * RPAD + lcol) * 4);
#pragma unroll
        for (int j = 0; j < 4; j++) cp16(dst + j * 16, src + j * 4);
        cp_commit();
    }

    for (int ci = 0; ci < NCHUNK; ci++) {
        // issue next chunk into the other buffer
        if (ci + 1 < NCHUNK) {
            int k0n = (ci + 1) * CHUNK;
            int gr = min(k0n + lrow, LL - 1);
            const float* src = tibase + (size_t)gr * DD + lcol;
            unsigned int dst = sbase +
                (unsigned int)((((ci + 1) & 1) * CHUNK * RPAD + lrow * RPAD + lcol) * 4);
#pragma unroll
            for (int j = 0; j < 4; j++) cp16(dst + j * 16, src + j * 4);
            cp_commit();
            cp_wait<1>();
        } else {
            cp_wait<0>();
        }
        __syncthreads();

        // compute from buffer ci&1
        int k0 = ci * CHUNK;
        int kg = k0 + kl;
        int kgc = min(kg, LL - 1);
        const float* brow = bbat + (size_t)kgc * DD + h * HS + half * 16;
        float4 b0 = *(const float4*)(brow + 0);
        float4 b1 = *(const float4*)(brow + 4);
        float4 b2 = *(const float4*)(brow + 8);
        float4 b3 = *(const float4*)(brow + 12);
        const float* ts = &ti_s[ci & 1][kl][h * HS + half * 16];
        float4 t0 = *(const float4*)(ts + 0);
        float4 t1 = *(const float4*)(ts + 4);
        float4 t2 = *(const float4*)(ts + 8);
        float4 t3 = *(const float4*)(ts + 12);

        float s1, s2;
        {
            float c0 = b0.x + t0.x, c1 = b0.y + t0.y, c2 = b0.z + t0.z, c3 = b0.w + t0.w;
            float d0 = b1.x + t1.x, d1 = b1.y + t1.y, d2 = b1.z + t1.z, d3 = b1.w + t1.w;
            float e0 = b2.x + t2.x, e1 = b2.y + t2.y, e2 = b2.z + t2.z, e3 = b2.w + t2.w;
            float f0 = b3.x + t3.x, f1 = b3.y + t3.y, f2 = b3.z + t3.z, f3 = b3.w + t3.w;
            s1 = av0.x*c0 + av0.y*c1 + av0.z*c2 + av0.w*c3
               + av1.x*d0 + av1.y*d1 + av1.z*d2 + av1.w*d3
               + av2.x*e0 + av2.y*e1 + av2.z*e2 + av2.w*e3
               + av3.x*f0 + av3.y*f1 + av3.z*f2 + av3.w*f3;
            s2 = c0*c0 + c1*c1 + c2*c2 + c3*c3
               + d0*d0 + d1*d1 + d2*d2 + d3*d3
               + e0*e0 + e1*e1 + e2*e2 + e3*e3
               + f0*f0 + f1*f1 + f2*f2 + f3*f3;
        }
        s1 += __shfl_xor_sync(0xffffffffu, s1, 16);
        s2 += __shfl_xor_sync(0xffffffffu, s2, 16);

        if (half == 0 && kg < LL) {
            float raw = s1 / (a2 * sqrtf(s2) + 1e-6f);
            if (mrow[kg]) raw = 0.f;
            s_row[h][kg] = raw;
        }
        __syncthreads();
    }
    __syncwarp();

    // write the row to global (coalesced) for pass 2
    for (int i = lane; i < LL; i += 32) g_raw[rowbase + i] = s_row[h][i];

    // ---- fused top-K (jax.lax.top_k tie semantics: ties -> lower index) ----
    float v[7];
#pragma unroll
    for (int i = 0; i < 7; i++) {
        int g = lane + i * 32;
        v[i] = (g < LL) ? s_row[h][g] : -FLT_MAX;
    }
    size_t bits_row = (size_t)(hb * LL + q) * 8;
    for (int it = 0; it < KTOP; it++) {
        float bv = -FLT_MAX;
        int bi = 1 << 30;
#pragma unroll
        for (int i = 0; i < 7; i++) {
            if (v[i] > bv) { bv = v[i]; bi = lane + i * 32; }
        }
#pragma unroll
        for (int off = 16; off; off >>= 1) {
            float ov = __shfl_xor_sync(0xffffffffu, bv, off);
            int   oi = __shfl_xor_sync(0xffffffffu, bi, off);
            if (ov > bv || (ov == bv && oi < bi)) { bv = ov; bi = oi; }
        }
        if (lane == (bi & 31)) v[bi >> 5] = -FLT_MAX;
        if (lane == 0) {
            atomicOr(&g_selbits[bits_row + (bi >> 5)], 1u << (bi & 31));
            atomicOr(&g_selbits[(size_t)(hb * LL + bi) * 8 + (q >> 5)], 1u << (q & 31));
        }
    }
}

// ---------------- Pass 2: compacted sparse matmuls + LayerNorm -----------
__global__ void out_kernel(const float* __restrict__ tm,
                           const float* __restrict__ gamma,
                           const float* __restrict__ beta,
                           float* __restrict__ out, int out_size) {
    int q = blockIdx.x, b = blockIdx.y;
    int t = threadIdx.x, h = t >> 5, lane = t & 31;
    int hb = h * BB + b;
    __shared__ short s_idx[8][LL];
    __shared__ float s_val[8][LL];
    __shared__ float rs[8];

    size_t base = (size_t)(hb * LL + q) * LL;
    size_t bits_row = (size_t)(hb * LL + q) * 8;
    int cnt = 0;
#pragma unroll
    for (int c = 0; c < 7; c++) {
        unsigned m = g_selbits[bits_row + c];    // broadcast load
        int i = c * 32 + lane;
        if ((m >> lane) & 1u) {
            int pos = cnt + __popc(m & ((1u << lane) - 1u));
            s_idx[h][pos] = (short)i;
            s_val[h][pos] = g_raw[base + i];
        }
        cnt += __popc(m);
    }
    __syncwarp();

    const float* tirow = tm + (size_t)(b * LL + q) * LL * DD + t;
    const float* wcol  = g_w + (size_t)b * LL * DD + t;
    float acc_o = 0.f, acc_t = 0.f;
#pragma unroll 8
    for (int p = 0; p < cnt; p++) {
        int k = s_idx[h][p];
        float r = s_val[h][p];
        acc_o += r * wcol[(size_t)k * DD];
        acc_t += r * tirow[(size_t)k * DD];
    }

    // LayerNorm over the 256 outputs of this block
    float sum = acc_o;
#pragma unroll
    for (int off = 16; off; off >>= 1) sum += __shfl_xor_sync(0xffffffffu, sum, off);
    if (lane == 0) rs[h] = sum;
    __syncthreads();
    float tot = 0.f;
#pragma unroll
    for (int i = 0; i < 8; i++) tot += rs[i];
    float mu = tot * (1.f / 256.f);
    __syncthreads();

    float d = acc_o - mu;
    float sq = d * d;
#pragma unroll
    for (int off = 16; off; off >>= 1) sq += __shfl_xor_sync(0xffffffffu, sq, off);
    if (lane == 0) rs[h] = sq;
    __syncthreads();
    float totq = 0.f;
#pragma unroll
    for (int i = 0; i < 8; i++) totq += rs[i];
    float var = totq * (1.f / 256.f);

    float ln = d * rsqrtf(var + 1e-8f) * gamma[t] + beta[t];
    size_t o = (size_t)(b * LL + q) * DD + t;
    out[o] = ln;
    if (out_size > LNELEM) out[LNELEM + o] = acc_t;
}

// ---------------- launch ----------------
extern "C" void kernel_launch(void* const* d_in, const int* in_sizes, int n_in,
                              void* d_out, int out_size) {
    const float* seqs    = (const float*)d_in[0];
    const void*  amask   = d_in[1];
    const float* tm      = (const float*)d_in[2];
    const float* conv1_w = (const float*)d_in[3];
    const float* conv1_b = (const float*)d_in[4];
    const float* conv2_w = (const float*)d_in[5];
    const float* conv2_b = (const float*)d_in[6];
    const float* W_w     = (const float*)d_in[7];
    const float* W_b     = (const float*)d_in[8];
    const float* ln_g    = (const float*)d_in[9];
    const float* ln_b    = (const float*)d_in[10];
    float* out = (float*)d_out;

    mask_kernel<<<1, 256>>>(amask);
    zero_sel_kernel<<<(HB * LL * 8 + 255) / 256, 256>>>();
    gemm3_kernel<<<dim3(DD / 64, NROW / 64, 3), 256>>>(
        seqs, conv1_w, conv1_b, conv2_w, conv2_b, W_w, W_b);
    raw_kernel<<<dim3(LL, BB), 256>>>(tm);
    out_kernel<<<dim3(LL, BB), 256>>>(tm, ln_g, ln_b, out, out_size);
}

// round 10
// speedup vs baseline: 1.1771x; 1.1771x over previous
#include <cuda_runtime.h>
#include <cuda_bf16.h>
#include <float.h>
#include <math.h>

// Problem constants
#define BB 8
#define LL 200
#define DD 256
#define HH 8
#define HS 32
#define HB 64          // H*B
#define KTOP 20
#define NROW 1600      // B*L
#define LNELEM 409600  // B*L*D

// ---------------- device scratch (no allocs allowed) ----------------
__device__ float g_a[NROW * DD];
__device__ float g_b[NROW * DD];
__device__ float g_w[NROW * DD];
__device__ float g_raw[(size_t)HB * LL * LL];
__device__ unsigned int g_selbits[(size_t)HB * LL * 8]; // topk bitmask, 8 words/row
__device__ unsigned char g_mask[LL * LL];

// ---------------- merged: mask dtype detect/convert + selbits zero -------
// Block 0 handles the attention mask; blocks 1..25 zero g_selbits (400KB).
__global__ void maskzero_kernel(const void* __restrict__ src) {
    if (blockIdx.x == 0) {
        __shared__ int flags[4];
        int t = threadIdx.x;
        if (t < 4) flags[t] = 0;
        __syncthreads();
        const unsigned char* p = (const unsigned char*)src;
        for (int i = t; i < LL * LL; i += 256) {
            if (p[i]) flags[i & 3] = 1;
        }
        __syncthreads();
        int dt;  // 0=u8, 1=i32, 2=f32
        if (flags[1]) dt = 0;
        else if (flags[2] | flags[3]) dt = 2;
        else dt = 1;
        for (int i = t; i < LL * LL; i += 256) {
            unsigned char m;
            if (dt == 0)      m = (p[i] != 0);
            else if (dt == 1) m = (((const int*)src)[i] != 0);
            else              m = (((const float*)src)[i] != 0.0f);
            g_mask[i] = m;
        }
    } else {
        int base = (blockIdx.x - 1) * 256 + threadIdx.x;
        for (int i = base; i < HB * LL * 8; i += 25 * 256) g_selbits[i] = 0u;
    }
}

// ---------------- 3 fused GEMMs: out = X @ W.T + bias ----------------
__global__ void gemm3_kernel(const float* __restrict__ X,
                             const float* __restrict__ W0, const float* __restrict__ B0,
                             const float* __restrict__ W1, const float* __restrict__ B1,
                             const float* __restrict__ W2, const float* __restrict__ B2) {
    const float* W; const float* Bv; float* O;
    if (blockIdx.z == 0)      { W = W0; Bv = B0; O = g_a; }
    else if (blockIdx.z == 1) { W = W1; Bv = B1; O = g_b; }
    else                      { W = W2; Bv = B2; O = g_w; }

    __shared__ float As[16][68];
    __shared__ float Bs[16][68];
    int i0 = blockIdx.y * 64;
    int o0 = blockIdx.x * 64;
    int t = threadIdx.x;
    int tx = t & 15, ty = t >> 4;
    int lr = t >> 2;
    int lc4 = (t & 3) * 4;

    float acc[4][4];
#pragma unroll
    for (int i = 0; i < 4; i++)
#pragma unroll
        for (int j = 0; j < 4; j++) acc[i][j] = 0.f;

    for (int k0 = 0; k0 < DD; k0 += 16) {
        float4 xa = *(const float4*)&X[(size_t)(i0 + lr) * DD + k0 + lc4];
        float4 wb = *(const float4*)&W[(size_t)(o0 + lr) * DD + k0 + lc4];
        As[lc4 + 0][lr] = xa.x; As[lc4 + 1][lr] = xa.y;
        As[lc4 + 2][lr] = xa.z; As[lc4 + 3][lr] = xa.w;
        Bs[lc4 + 0][lr] = wb.x; Bs[lc4 + 1][lr] = wb.y;
        Bs[lc4 + 2][lr] = wb.z; Bs[lc4 + 3][lr] = wb.w;
        __syncthreads();
#pragma unroll
        for (int kk = 0; kk < 16; kk++) {
            float4 a4 = *(const float4*)&As[kk][ty * 4];
            float4 b4 = *(const float4*)&Bs[kk][tx * 4];
            float am[4] = {a4.x, a4.y, a4.z, a4.w};
            float bn[4] = {b4.x, b4.y, b4.z, b4.w};
#pragma unroll
            for (int mi = 0; mi < 4; mi++)
#pragma unroll
                for (int ni = 0; ni < 4; ni++) acc[mi][ni] += am[mi] * bn[ni];
        }
        __syncthreads();
    }
#pragma unroll
    for (int mi = 0; mi < 4; mi++) {
#pragma unroll
        for (int ni = 0; ni < 4; ni++) {
            int oo = o0 + tx * 4 + ni;
            O[(size_t)(i0 + ty * 4 + mi) * DD + oo] = acc[mi][ni] + Bv[oo];
        }
    }
}

// ---------------- Pass 1 (R1-proven loop) + fused top-K ------------------
// Block = (q, b), warp h = head h. lanes: ksub = lane/8 (4 k at a time),
// j8 = lane%8 covers HS=32 via float4. 6 SHFL per 4 k. Row kept in smem,
// then warp-local top-K scatters the symmetric selection bitmask.
__global__ void __launch_bounds__(256, 6) raw_kernel(const float* __restrict__ tm) {
    int q = blockIdx.x, b = blockIdx.y;
    int t = threadIdx.x, h = t >> 5, lane = t & 31;
    int ksub = lane >> 3, j8 = lane & 7;
    __shared__ float s_row[8][LL];

    const float* arow = g_a + (size_t)(b * LL + q) * DD + h * HS + j8 * 4;
    float4 a4 = *(const float4*)arow;
    float s = a4.x * a4.x + a4.y * a4.y + a4.z * a4.z + a4.w * a4.w;
#pragma unroll
    for (int off = 4; off; off >>= 1) s += __shfl_xor_sync(0xffffffffu, s, off);
    float a2 = sqrtf(s);

    const float* tibase = tm + (size_t)(b * LL + q) * LL * DD + h * HS + j8 * 4;
    const float* bbase  = g_b + (size_t)b * LL * DD + h * HS + j8 * 4;
    int hb = h * BB + b;
    size_t rowbase = (size_t)(hb * LL + q) * LL;
    const unsigned char* mrow = g_mask + q * LL;

    for (int kb = 0; kb < LL; kb += 4) {
        int k = kb + ksub;
        float4 tv = *(const float4*)(tibase + (size_t)k * DD);
        float4 bv = *(const float4*)(bbase + (size_t)k * DD);
        float c0 = bv.x + tv.x, c1 = bv.y + tv.y;
        float c2 = bv.z + tv.z, c3 = bv.w + tv.w;
        float s1 = a4.x * c0 + a4.y * c1 + a4.z * c2 + a4.w * c3;
        float s2 = c0 * c0 + c1 * c1 + c2 * c2 + c3 * c3;
#pragma unroll
        for (int off = 4; off; off >>= 1) {
            s1 += __shfl_xor_sync(0xffffffffu, s1, off);
            s2 += __shfl_xor_sync(0xffffffffu, s2, off);
        }
        if (j8 == 0) {
            float raw = s1 / (a2 * sqrtf(s2) + 1e-6f);
            if (mrow[k]) raw = 0.f;
            s_row[h][k] = raw;
        }
    }
    __syncwarp();

    // write the row to global (coalesced) for pass 2
    for (int i = lane; i < LL; i += 32) g_raw[rowbase + i] = s_row[h][i];

    // ---- fused top-K (jax.lax.top_k tie semantics: ties -> lower index) ----
    float v[7];
#pragma unroll
    for (int i = 0; i < 7; i++) {
        int g = lane + i * 32;
        v[i] = (g < LL) ? s_row[h][g] : -FLT_MAX;
    }
    size_t bits_row = (size_t)(hb * LL + q) * 8;
    for (int it = 0; it < KTOP; it++) {
        float bv = -FLT_MAX;
        int bi = 1 << 30;
#pragma unroll
        for (int i = 0; i < 7; i++) {
            if (v[i] > bv) { bv = v[i]; bi = lane + i * 32; }
        }
#pragma unroll
        for (int off = 16; off; off >>= 1) {
            float ov = __shfl_xor_sync(0xffffffffu, bv, off);
            int   oi = __shfl_xor_sync(0xffffffffu, bi, off);
            if (ov > bv || (ov == bv && oi < bi)) { bv = ov; bi = oi; }
        }
        if (lane == (bi & 31)) v[bi >> 5] = -FLT_MAX;
        if (lane == 0) {
            atomicOr(&g_selbits[bits_row + (bi >> 5)], 1u << (bi & 31));
            atomicOr(&g_selbits[(size_t)(hb * LL + bi) * 8 + (q >> 5)], 1u << (q & 31));
        }
    }
}

// ---------------- Pass 2: compacted sparse matmuls + LayerNorm -----------
__global__ void out_kernel(const float* __restrict__ tm,
                           const float* __restrict__ gamma,
                           const float* __restrict__ beta,
                           float* __restrict__ out, int out_size) {
    int q = blockIdx.x, b = blockIdx.y;
    int t = threadIdx.x, h = t >> 5, lane = t & 31;
    int hb = h * BB + b;
    __shared__ short s_idx[8][LL];
    __shared__ float s_val[8][LL];
    __shared__ float rs[8];

    size_t base = (size_t)(hb * LL + q) * LL;
    size_t bits_row = (size_t)(hb * LL + q) * 8;
    int cnt = 0;
#pragma unroll
    for (int c = 0; c < 7; c++) {
        unsigned m = g_selbits[bits_row + c];    // broadcast load
        int i = c * 32 + lane;
        if ((m >> lane) & 1u) {
            int pos = cnt + __popc(m & ((1u << lane) - 1u));
            s_idx[h][pos] = (short)i;
            s_val[h][pos] = g_raw[base + i];
        }
        cnt += __popc(m);
    }
    __syncwarp();

    const float* tirow = tm + (size_t)(b * LL + q) * LL * DD + t;
    const float* wcol  = g_w + (size_t)b * LL * DD + t;
    float acc_o = 0.f, acc_t = 0.f;
#pragma unroll 8
    for (int p = 0; p < cnt; p++) {
        int k = s_idx[h][p];
        float r = s_val[h][p];
        acc_o += r * wcol[(size_t)k * DD];
        acc_t += r * tirow[(size_t)k * DD];
    }

    // LayerNorm over the 256 outputs of this block
    float sum = acc_o;
#pragma unroll
    for (int off = 16; off; off >>= 1) sum += __shfl_xor_sync(0xffffffffu, sum, off);
    if (lane == 0) rs[h] = sum;
    __syncthreads();
    float tot = 0.f;
#pragma unroll
    for (int i = 0; i < 8; i++) tot += rs[i];
    float mu = tot * (1.f / 256.f);
    __syncthreads();

    float d = acc_o - mu;
    float sq = d * d;
#pragma unroll
    for (int off = 16; off; off >>= 1) sq += __shfl_xor_sync(0xffffffffu, sq, off);
    if (lane == 0) rs[h] = sq;
    __syncthreads();
    float totq = 0.f;
#pragma unroll
    for (int i = 0; i < 8; i++) totq += rs[i];
    float var = totq * (1.f / 256.f);

    float ln = d * rsqrtf(var + 1e-8f) * gamma[t] + beta[t];
    size_t o = (size_t)(b * LL + q) * DD + t;
    out[o] = ln;
    if (out_size > LNELEM) out[LNELEM + o] = acc_t;
}

// ---------------- launch ----------------
extern "C" void kernel_launch(void* const* d_in, const int* in_sizes, int n_in,
                              void* d_out, int out_size) {
    const float* seqs    = (const float*)d_in[0];
    const void*  amask   = d_in[1];
    const float* tm      = (const float*)d_in[2];
    const float* conv1_w = (const float*)d_in[3];
    const float* conv1_b = (const float*)d_in[4];
    const float* conv2_w = (const float*)d_in[5];
    const float* conv2_b = (const float*)d_in[6];
    const float* W_w     = (const float*)d_in[7];
    const float* W_b     = (const float*)d_in[8];
    const float* ln_g    = (const float*)d_in[9];
    const float* ln_b    = (const float*)d_in[10];
    float* out = (float*)d_out;

    gemm3_kernel<<<dim3(DD / 64, NROW / 64, 3), 256>>>(
        seqs, conv1_w, conv1_b, conv2_w, conv2_b, W_w, W_b);
    maskzero_kernel<<<26, 256>>>(amask);
    raw_kernel<<<dim3(LL, BB), 256>>>(tm);
    out_kernel<<<dim3(LL, BB), 256>>>(tm, ln_g, ln_b, out, out_size);
}

// round 11
// speedup vs baseline: 1.3621x; 1.1572x over previous
#include <cuda_runtime.h>
#include <cuda_bf16.h>
#include <float.h>
#include <math.h>

// Problem constants
#define BB 8
#define LL 200
#define DD 256
#define HH 8
#define HS 32
#define HB 64          // H*B
#define KTOP 20
#define NROW 1600      // B*L
#define LNELEM 409600  // B*L*D
#define PADL 216       // compacted list capacity (>=200, mult of 8)

// ---------------- device scratch (no allocs allowed) ----------------
__device__ float g_a[NROW * DD];
__device__ float g_b[NROW * DD];
__device__ float g_w[NROW * DD];
__device__ float g_raw[(size_t)HB * LL * LL];
__device__ unsigned int g_selbits[(size_t)HB * LL * 8]; // topk bitmask, 8 words/row
__device__ unsigned char g_mask[LL * LL];

// ---------------- 3 fused GEMMs + mask convert + selbits zero ------------
// gridDim = (4, 25, 4). z<3: GEMM out = X @ W.T + bias into g_a/g_b/g_w.
// z==3: 100 blocks; block 0 converts the attention mask, blocks 1..99 zero
// the selection bitmask (overlapped with the GEMM slices).
__global__ void gemm3mz_kernel(const float* __restrict__ X,
                               const float* __restrict__ W0, const float* __restrict__ B0,
                               const float* __restrict__ W1, const float* __restrict__ B1,
                               const float* __restrict__ W2, const float* __restrict__ B2,
                               const void* __restrict__ msrc) {
    if (blockIdx.z == 3) {
        int bi = blockIdx.y * 4 + blockIdx.x;   // 0..99
        int t = threadIdx.x;
        if (bi == 0) {
            __shared__ int flags[4];
            if (t < 4) flags[t] = 0;
            __syncthreads();
            const unsigned char* p = (const unsigned char*)msrc;
            for (int i = t; i < LL * LL; i += 256) {
                if (p[i]) flags[i & 3] = 1;
            }
            __syncthreads();
            int dt;  // 0=u8, 1=i32, 2=f32
            if (flags[1]) dt = 0;
            else if (flags[2] | flags[3]) dt = 2;
            else dt = 1;
            for (int i = t; i < LL * LL; i += 256) {
                unsigned char m;
                if (dt == 0)      m = (p[i] != 0);
                else if (dt == 1) m = (((const int*)msrc)[i] != 0);
                else              m = (((const float*)msrc)[i] != 0.0f);
                g_mask[i] = m;
            }
        } else {
            for (int i = (bi - 1) * 256 + t; i < HB * LL * 8; i += 99 * 256)
                g_selbits[i] = 0u;
        }
        return;
    }

    const float* W; const float* Bv; float* O;
    if (blockIdx.z == 0)      { W = W0; Bv = B0; O = g_a; }
    else if (blockIdx.z == 1) { W = W1; Bv = B1; O = g_b; }
    else                      { W = W2; Bv = B2; O = g_w; }

    __shared__ float As[16][68];
    __shared__ float Bs[16][68];
    int i0 = blockIdx.y * 64;
    int o0 = blockIdx.x * 64;
    int t = threadIdx.x;
    int tx = t & 15, ty = t >> 4;
    int lr = t >> 2;
    int lc4 = (t & 3) * 4;

    float acc[4][4];
#pragma unroll
    for (int i = 0; i < 4; i++)
#pragma unroll
        for (int j = 0; j < 4; j++) acc[i][j] = 0.f;

    for (int k0 = 0; k0 < DD; k0 += 16) {
        float4 xa = *(const float4*)&X[(size_t)(i0 + lr) * DD + k0 + lc4];
        float4 wb = *(const float4*)&W[(size_t)(o0 + lr) * DD + k0 + lc4];
        As[lc4 + 0][lr] = xa.x; As[lc4 + 1][lr] = xa.y;
        As[lc4 + 2][lr] = xa.z; As[lc4 + 3][lr] = xa.w;
        Bs[lc4 + 0][lr] = wb.x; Bs[lc4 + 1][lr] = wb.y;
        Bs[lc4 + 2][lr] = wb.z; Bs[lc4 + 3][lr] = wb.w;
        __syncthreads();
#pragma unroll
        for (int kk = 0; kk < 16; kk++) {
            float4 a4 = *(const float4*)&As[kk][ty * 4];
            float4 b4 = *(const float4*)&Bs[kk][tx * 4];
            float am[4] = {a4.x, a4.y, a4.z, a4.w};
            float bn[4] = {b4.x, b4.y, b4.z, b4.w};
#pragma unroll
            for (int mi = 0; mi < 4; mi++)
#pragma unroll
                for (int ni = 0; ni < 4; ni++) acc[mi][ni] += am[mi] * bn[ni];
        }
        __syncthreads();
    }
#pragma unroll
    for (int mi = 0; mi < 4; mi++) {
#pragma unroll
        for (int ni = 0; ni < 4; ni++) {
            int oo = o0 + tx * 4 + ni;
            O[(size_t)(i0 + ty * 4 + mi) * DD + oo] = acc[mi][ni] + Bv[oo];
        }
    }
}

// ---------------- Pass 1 (R1-proven loop) + fused top-K ------------------
// Block = (q, b), warp h = head h. No launch_bounds — let regs float.
__global__ void raw_kernel(const float* __restrict__ tm) {
    int q = blockIdx.x, b = blockIdx.y;
    int t = threadIdx.x, h = t >> 5, lane = t & 31;
    int ksub = lane >> 3, j8 = lane & 7;
    __shared__ float s_row[8][LL];

    const float* arow = g_a + (size_t)(b * LL + q) * DD + h * HS + j8 * 4;
    float4 a4 = *(const float4*)arow;
    float s = a4.x * a4.x + a4.y * a4.y + a4.z * a4.z + a4.w * a4.w;
#pragma unroll
    for (int off = 4; off; off >>= 1) s += __shfl_xor_sync(0xffffffffu, s, off);
    float a2 = sqrtf(s);

    const float* tibase = tm + (size_t)(b * LL + q) * LL * DD + h * HS + j8 * 4;
    const float* bbase  = g_b + (size_t)b * LL * DD + h * HS + j8 * 4;
    int hb = h * BB + b;
    size_t rowbase = (size_t)(hb * LL + q) * LL;
    const unsigned char* mrow = g_mask + q * LL;

    for (int kb = 0; kb < LL; kb += 4) {
        int k = kb + ksub;
        float4 tv = *(const float4*)(tibase + (size_t)k * DD);
        float4 bv = *(const float4*)(bbase + (size_t)k * DD);
        float c0 = bv.x + tv.x, c1 = bv.y + tv.y;
        float c2 = bv.z + tv.z, c3 = bv.w + tv.w;
        float s1 = a4.x * c0 + a4.y * c1 + a4.z * c2 + a4.w * c3;
        float s2 = c0 * c0 + c1 * c1 + c2 * c2 + c3 * c3;
#pragma unroll
        for (int off = 4; off; off >>= 1) {
            s1 += __shfl_xor_sync(0xffffffffu, s1, off);
            s2 += __shfl_xor_sync(0xffffffffu, s2, off);
        }
        if (j8 == 0) {
            float raw = s1 / (a2 * sqrtf(s2) + 1e-6f);
            if (mrow[k]) raw = 0.f;
            s_row[h][k] = raw;
        }
    }
    __syncwarp();

    // write the row to global (coalesced) for pass 2
    for (int i = lane; i < LL; i += 32) g_raw[rowbase + i] = s_row[h][i];

    // ---- fused top-K (jax.lax.top_k tie semantics: ties -> lower index) ----
    float v[7];
#pragma unroll
    for (int i = 0; i < 7; i++) {
        int g = lane + i * 32;
        v[i] = (g < LL) ? s_row[h][g] : -FLT_MAX;
    }
    size_t bits_row = (size_t)(hb * LL + q) * 8;
    for (int it = 0; it < KTOP; it++) {
        float bv = -FLT_MAX;
        int bi = 1 << 30;
#pragma unroll
        for (int i = 0; i < 7; i++) {
            if (v[i] > bv) { bv = v[i]; bi = lane + i * 32; }
        }
#pragma unroll
        for (int off = 16; off; off >>= 1) {
            float ov = __shfl_xor_sync(0xffffffffu, bv, off);
            int   oi = __shfl_xor_sync(0xffffffffu, bi, off);
            if (ov > bv || (ov == bv && oi < bi)) { bv = ov; bi = oi; }
        }
        if (lane == (bi & 31)) v[bi >> 5] = -FLT_MAX;
        if (lane == 0) {
            atomicOr(&g_selbits[bits_row + (bi >> 5)], 1u << (bi & 31));
            atomicOr(&g_selbits[(size_t)(hb * LL + bi) * 8 + (q >> 5)], 1u << (q & 31));
        }
    }
}

// ---------------- Pass 2: compacted + padded gather, LayerNorm -----------
// Compacted list padded to a multiple of 16 with (idx=valid, val=0) so the
// gather is branch-free with 32 independent LDGs in flight per batch.
__global__ void out_kernel(const float* __restrict__ tm,
                           const float* __restrict__ gamma,
                           const float* __restrict__ beta,
                           float* __restrict__ out, int out_size) {
    int q = blockIdx.x, b = blockIdx.y;
    int t = threadIdx.x, h = t >> 5, lane = t & 31;
    int hb = h * BB + b;
    __shared__ short s_idx[8][PADL];
    __shared__ float s_val[8][PADL];
    __shared__ float rs[8];

    size_t base = (size_t)(hb * LL + q) * LL;
    size_t bits_row = (size_t)(hb * LL + q) * 8;
    int cnt = 0;
#pragma unroll
    for (int c = 0; c < 7; c++) {
        unsigned m = g_selbits[bits_row + c];    // broadcast load
        int i = c * 32 + lane;
        if ((m >> lane) & 1u) {
            int pos = cnt + __popc(m & ((1u << lane) - 1u));
            s_idx[h][pos] = (short)i;
            s_val[h][pos] = g_raw[base + i];
        }
        cnt += __popc(m);
    }
    __syncwarp();
    int cnt_pad = (cnt + 15) & ~15;
    // pad with benign entries (top-K guarantees cnt >= KTOP >= 1)
    for (int i = cnt + lane; i < cnt_pad; i += 32) {
        s_idx[h][i] = s_idx[h][0];
        s_val[h][i] = 0.f;
    }
    __syncwarp();

    const float* tirow = tm + (size_t)(b * LL + q) * LL * DD + t;
    const float* wcol  = g_w + (size_t)b * LL * DD + t;
    float acc_o = 0.f, acc_t = 0.f;
    for (int p = 0; p < cnt_pad; p += 16) {
#pragma unroll
        for (int u = 0; u < 16; u++) {
            int k = s_idx[h][p + u];
            float r = s_val[h][p + u];
            acc_o += r * wcol[(size_t)k * DD];
            acc_t += r * tirow[(size_t)k * DD];
        }
    }

    // LayerNorm over the 256 outputs of this block
    float sum = acc_o;
#pragma unroll
    for (int off = 16; off; off >>= 1) sum += __shfl_xor_sync(0xffffffffu, sum, off);
    if (lane == 0) rs[h] = sum;
    __syncthreads();
    float tot = 0.f;
#pragma unroll
    for (int i = 0; i < 8; i++) tot += rs[i];
    float mu = tot * (1.f / 256.f);
    __syncthreads();

    float d = acc_o - mu;
    float sq = d * d;
#pragma unroll
    for (int off = 16; off; off >>= 1) sq += __shfl_xor_sync(0xffffffffu, sq, off);
    if (lane == 0) rs[h] = sq;
    __syncthreads();
    float totq = 0.f;
#pragma unroll
    for (int i = 0; i < 8; i++) totq += rs[i];
    float var = totq * (1.f / 256.f);

    float ln = d * rsqrtf(var + 1e-8f) * gamma[t] + beta[t];
    size_t o = (size_t)(b * LL + q) * DD + t;
    out[o] = ln;
    if (out_size > LNELEM) out[LNELEM + o] = acc_t;
}

// ---------------- launch ----------------
extern "C" void kernel_launch(void* const* d_in, const int* in_sizes, int n_in,
                              void* d_out, int out_size) {
    const float* seqs    = (const float*)d_in[0];
    const void*  amask   = d_in[1];
    const float* tm      = (const float*)d_in[2];
    const float* conv1_w = (const float*)d_in[3];
    const float* conv1_b = (const float*)d_in[4];
    const float* conv2_w = (const float*)d_in[5];
    const float* conv2_b = (const float*)d_in[6];
    const float* W_w     = (const float*)d_in[7];
    const float* W_b     = (const float*)d_in[8];
    const float* ln_g    = (const float*)d_in[9];
    const float* ln_b    = (const float*)d_in[10];
    float* out = (float*)d_out;

    gemm3mz_kernel<<<dim3(DD / 64, NROW / 64, 4), 256>>>(
        seqs, conv1_w, conv1_b, conv2_w, conv2_b, W_w, W_b, amask);
    raw_kernel<<<dim3(LL, BB), 256>>>(tm);
    out_kernel<<<dim3(LL, BB), 256>>>(tm, ln_g, ln_b, out, out_size);
}

// round 13
// speedup vs baseline: 1.4166x; 1.0400x over previous
#include <cuda_runtime.h>
#include <cuda_bf16.h>
#include <float.h>
#include <math.h>

// Problem constants
#define BB 8
#define LL 200
#define DD 256
#define HH 8
#define HS 32
#define HB 64          // H*B
#define KTOP 20
#define NROW 1600      // B*L
#define LNELEM 409600  // B*L*D
#define PADL 216       // compacted list capacity (>=200, mult of 8)

// ---------------- device scratch (no allocs allowed) ----------------
__device__ float g_a[NROW * DD];
__device__ float g_b[NROW * DD];
__device__ float g_w[NROW * DD];
__device__ float g_raw[(size_t)HB * LL * LL];
__device__ unsigned int g_selbits[(size_t)HB * LL * 8]; // topk bitmask, 8 words/row
__device__ unsigned char g_mask[LL * LL];

// ---------------- 3 fused GEMMs + mask convert + selbits zero ------------
// gridDim = (4, 50, 4). z<3: GEMM out = X @ W.T + bias, tile 32 rows x 64
// cols, k-chunk 32, register double-buffered. z==3: 200 blocks; block 0
// converts the attention mask, the rest zero the selection bitmask.
__global__ void gemm3mz_kernel(const float* __restrict__ X,
                               const float* __restrict__ W0, const float* __restrict__ B0,
                               const float* __restrict__ W1, const float* __restrict__ B1,
                               const float* __restrict__ W2, const float* __restrict__ B2,
                               const void* __restrict__ msrc) {
    if (blockIdx.z == 3) {
        int bi = blockIdx.y * 4 + blockIdx.x;   // 0..199
        int t = threadIdx.x;
        if (bi == 0) {
            __shared__ int flags[4];
            if (t < 4) flags[t] = 0;
            __syncthreads();
            const unsigned char* p = (const unsigned char*)msrc;
            for (int i = t; i < LL * LL; i += 256) {
                if (p[i]) flags[i & 3] = 1;
            }
            __syncthreads();
            int dt;  // 0=u8, 1=i32, 2=f32
            if (flags[1]) dt = 0;
            else if (flags[2] | flags[3]) dt = 2;
            else dt = 1;
            for (int i = t; i < LL * LL; i += 256) {
                unsigned char m;
                if (dt == 0)      m = (p[i] != 0);
                else if (dt == 1) m = (((const int*)msrc)[i] != 0);
                else              m = (((const float*)msrc)[i] != 0.0f);
                g_mask[i] = m;
            }
        } else {
            for (int i = (bi - 1) * 256 + t; i < HB * LL * 8; i += 199 * 256)
                g_selbits[i] = 0u;
        }
        return;
    }

    const float* W; const float* Bv; float* O;
    if (blockIdx.z == 0)      { W = W0; Bv = B0; O = g_a; }
    else if (blockIdx.z == 1) { W = W1; Bv = B1; O = g_b; }
    else                      { W = W2; Bv = B2; O = g_w; }

    __shared__ float As[32][38];   // [k][m-row]
    __shared__ float Bs[32][68];   // [k][n-row]
    int i0 = blockIdx.y * 32;      // M tile (50 tiles)
    int o0 = blockIdx.x * 64;      // N tile (4 tiles)
    int t = threadIdx.x;
    int tx = t & 15, ty = t >> 4;

    // loader mappings
    int xrow = t >> 3;             // 0..31
    int xkb  = (t & 7) * 4;        // k offset for X float4
    int wrow = t >> 2;             // 0..63
    int wkb  = (t & 3) * 8;        // k offset for W, two float4

    const float* xsrc = &X[(size_t)(i0 + xrow) * DD + xkb];
    const float* wsrc = &W[(size_t)(o0 + wrow) * DD + wkb];

    float4 xa = *(const float4*)xsrc;
    float4 wb0 = *(const float4*)(wsrc + 0);
    float4 wb1 = *(const float4*)(wsrc + 4);

    float acc[2][4];
#pragma unroll
    for (int i = 0; i < 2; i++)
#pragma unroll
        for (int j = 0; j < 4; j++) acc[i][j] = 0.f;

    for (int k0 = 0; k0 < DD; k0 += 32) {
        As[xkb + 0][xrow] = xa.x; As[xkb + 1][xrow] = xa.y;
        As[xkb + 2][xrow] = xa.z; As[xkb + 3][xrow] = xa.w;
        Bs[wkb + 0][wrow] = wb0.x; Bs[wkb + 1][wrow] = wb0.y;
        Bs[wkb + 2][wrow] = wb0.z; Bs[wkb + 3][wrow] = wb0.w;
        Bs[wkb + 4][wrow] = wb1.x; Bs[wkb + 5][wrow] = wb1.y;
        Bs[wkb + 6][wrow] = wb1.z; Bs[wkb + 7][wrow] = wb1.w;
        __syncthreads();
        if (k0 + 32 < DD) {   // prefetch next chunk while computing this one
            xa  = *(const float4*)(xsrc + k0 + 32);
            wb0 = *(const float4*)(wsrc + k0 + 32);
            wb1 = *(const float4*)(wsrc + k0 + 36);
        }
#pragma unroll
        for (int kk = 0; kk < 32; kk++) {
            float2 a2 = *(const float2*)&As[kk][ty * 2];
            float4 b4 = *(const float4*)&Bs[kk][tx * 4];
            acc[0][0] += a2.x * b4.x; acc[0][1] += a2.x * b4.y;
            acc[0][2] += a2.x * b4.z; acc[0][3] += a2.x * b4.w;
            acc[1][0] += a2.y * b4.x; acc[1][1] += a2.y * b4.y;
            acc[1][2] += a2.y * b4.z; acc[1][3] += a2.y * b4.w;
        }
        __syncthreads();
    }
#pragma unroll
    for (int mi = 0; mi < 2; mi++) {
#pragma unroll
        for (int ni = 0; ni < 4; ni++) {
            int oo = o0 + tx * 4 + ni;
            O[(size_t)(i0 + ty * 2 + mi) * DD + oo] = acc[mi][ni] + Bv[oo];
        }
    }
}

// ---------------- Pass 1: 4-lanes-per-k geometry + fused top-K -----------
// Block = (q, b), warp h = head h. lanes: ksub = lane/4 covers 8 k per
// iteration; j4 = lane%4 owns 8 floats (2 float4) of the head dim.
// Reduction over the 4-lane group = 2 SHFL stages -> 4 SHFL per 8 k
// (3x fewer than the 6-per-4k R1 loop). Same plain load pattern.
__global__ void raw_kernel(const float* __restrict__ tm) {
    int q = blockIdx.x, b = blockIdx.y;
    int t = threadIdx.x, h = t >> 5, lane = t & 31;
    int ksub = lane >> 2, j4 = lane & 3;
    __shared__ float s_row[8][LL];

    // a fragment: 8 floats of head h owned by this lane
    const float* arow = g_a + (size_t)(b * LL + q) * DD + h * HS + j4 * 8;
    float4 af0 = *(const float4*)(arow + 0);
    float4 af1 = *(const float4*)(arow + 4);
    float s = af0.x*af0.x + af0.y*af0.y + af0.z*af0.z + af0.w*af0.w
            + af1.x*af1.x + af1.y*af1.y + af1.z*af1.z + af1.w*af1.w;
    s += __shfl_xor_sync(0xffffffffu, s, 1);
    s += __shfl_xor_sync(0xffffffffu, s, 2);
    float a2 = sqrtf(s);

    const float* tibase = tm + (size_t)(b * LL + q) * LL * DD + h * HS + j4 * 8;
    const float* bbase  = g_b + (size_t)b * LL * DD + h * HS + j4 * 8;
    int hb = h * BB + b;
    size_t rowbase = (size_t)(hb * LL + q) * LL;
    const unsigned char* mrow = g_mask + q * LL;

    for (int kb = 0; kb < LL; kb += 8) {
        int k = kb + ksub;
        float4 tv0 = *(const float4*)(tibase + (size_t)k * DD + 0);
        float4 tv1 = *(const float4*)(tibase + (size_t)k * DD + 4);
        float4 bv0 = *(const float4*)(bbase + (size_t)k * DD + 0);
        float4 bv1 = *(const float4*)(bbase + (size_t)k * DD + 4);
        float c0 = bv0.x + tv0.x, c1 = bv0.y + tv0.y;
        float c2 = bv0.z + tv0.z, c3 = bv0.w + tv0.w;
        float c4 = bv1.x + tv1.x, c5 = bv1.y + tv1.y;
        float c6 = bv1.z + tv1.z, c7 = bv1.w + tv1.w;
        float s1 = af0.x*c0 + af0.y*c1 + af0.z*c2 + af0.w*c3
                 + af1.x*c4 + af1.y*c5 + af1.z*c6 + af1.w*c7;
        float s2 = c0*c0 + c1*c1 + c2*c2 + c3*c3
                 + c4*c4 + c5*c5 + c6*c6 + c7*c7;
        s1 += __shfl_xor_sync(0xffffffffu, s1, 1);
        s2 += __shfl_xor_sync(0xffffffffu, s2, 1);
        s1 += __shfl_xor_sync(0xffffffffu, s1, 2);
        s2 += __shfl_xor_sync(0xffffffffu, s2, 2);
        if (j4 == 0) {
            float raw = s1 / (a2 * sqrtf(s2) + 1e-6f);
            if (mrow[k]) raw = 0.f;
            s_row[h][k] = raw;
        }
    }
    __syncwarp();

    // write the row to global (coalesced) for pass 2
    for (int i = lane; i < LL; i += 32) g_raw[rowbase + i] = s_row[h][i];

    // ---- fused top-K (jax.lax.top_k tie semantics: ties -> lower index) ----
    float v[7];
#pragma unroll
    for (int i = 0; i < 7; i++) {
        int g = lane + i * 32;
        v[i] = (g < LL) ? s_row[h][g] : -FLT_MAX;
    }
    size_t bits_row = (size_t)(hb * LL + q) * 8;
    for (int it = 0; it < KTOP; it++) {
        float bv = -FLT_MAX;
        int bi = 1 << 30;
#pragma unroll
        for (int i = 0; i < 7; i++) {
            if (v[i] > bv) { bv = v[i]; bi = lane + i * 32; }
        }
#pragma unroll
        for (int off = 16; off; off >>= 1) {
            float ov = __shfl_xor_sync(0xffffffffu, bv, off);
            int   oi = __shfl_xor_sync(0xffffffffu, bi, off);
            if (ov > bv || (ov == bv && oi < bi)) { bv = ov; bi = oi; }
        }
        if (lane == (bi & 31)) v[bi >> 5] = -FLT_MAX;
        if (lane == 0) {
            atomicOr(&g_selbits[bits_row + (bi >> 5)], 1u << (bi & 31));
            atomicOr(&g_selbits[(size_t)(hb * LL + bi) * 8 + (q >> 5)], 1u << (q & 31));
        }
    }
}

// ---------------- Pass 2: compacted + padded gather, LayerNorm -----------
__global__ void out_kernel(const float* __restrict__ tm,
                           const float* __restrict__ gamma,
                           const float* __restrict__ beta,
                           float* __restrict__ out, int out_size) {
    int q = blockIdx.x, b = blockIdx.y;
    int t = threadIdx.x, h = t >> 5, lane = t & 31;
    int hb = h * BB + b;
    __shared__ short s_idx[8][PADL];
    __shared__ float s_val[8][PADL];
    __shared__ float rs[8];

    size_t base = (size_t)(hb * LL + q) * LL;
    size_t bits_row = (size_t)(hb * LL + q) * 8;
    int cnt = 0;
#pragma unroll
    for (int c = 0; c < 7; c++) {
        unsigned m = g_selbits[bits_row + c];    // broadcast load
        int i = c * 32 + lane;
        if ((m >> lane) & 1u) {
            int pos = cnt + __popc(m & ((1u << lane) - 1u));
            s_idx[h][pos] = (short)i;
            s_val[h][pos] = g_raw[base + i];
        }
        cnt += __popc(m);
    }
    __syncwarp();
    int cnt_pad = (cnt + 15) & ~15;
    for (int i = cnt + lane; i < cnt_pad; i += 32) {
        s_idx[h][i] = s_idx[h][0];
        s_val[h][i] = 0.f;
    }
    __syncwarp();

    const float* tirow = tm + (size_t)(b * LL + q) * LL * DD + t;
    const float* wcol  = g_w + (size_t)b * LL * DD + t;
    float acc_o = 0.f, acc_t = 0.f;
    for (int p = 0; p < cnt_pad; p += 16) {
#pragma unroll
        for (int u = 0; u < 16; u++) {
            int k = s_idx[h][p + u];
            float r = s_val[h][p + u];
            acc_o += r * wcol[(size_t)k * DD];
            acc_t += r * tirow[(size_t)k * DD];
        }
    }

    // LayerNorm over the 256 outputs of this block
    float sum = acc_o;
#pragma unroll
    for (int off = 16; off; off >>= 1) sum += __shfl_xor_sync(0xffffffffu, sum, off);
    if (lane == 0) rs[h] = sum;
    __syncthreads();
    float tot = 0.f;
#pragma unroll
    for (int i = 0; i < 8; i++) tot += rs[i];
    float mu = tot * (1.f / 256.f);
    __syncthreads();

    float d = acc_o - mu;
    float sq = d * d;
#pragma unroll
    for (int off = 16; off; off >>= 1) sq += __shfl_xor_sync(0xffffffffu, sq, off);
    if (lane == 0) rs[h] = sq;
    __syncthreads();
    float totq = 0.f;
#pragma unroll
    for (int i = 0; i < 8; i++) totq += rs[i];
    float var = totq * (1.f / 256.f);

    float ln = d * rsqrtf(var + 1e-8f) * gamma[t] + beta[t];
    size_t o = (size_t)(b * LL + q) * DD + t;
    out[o] = ln;
    if (out_size > LNELEM) out[LNELEM + o] = acc_t;
}

// ---------------- launch ----------------
extern "C" void kernel_launch(void* const* d_in, const int* in_sizes, int n_in,
                              void* d_out, int out_size) {
    const float* seqs    = (const float*)d_in[0];
    const void*  amask   = d_in[1];
    const float* tm      = (const float*)d_in[2];
    const float* conv1_w = (const float*)d_in[3];
    const float* conv1_b = (const float*)d_in[4];
    const float* conv2_w = (const float*)d_in[5];
    const float* conv2_b = (const float*)d_in[6];
    const float* W_w     = (const float*)d_in[7];
    const float* W_b     = (const float*)d_in[8];
    const float* ln_g    = (const float*)d_in[9];
    const float* ln_b    = (const float*)d_in[10];
    float* out = (float*)d_out;

    gemm3mz_kernel<<<dim3(4, 50, 4), 256>>>(
        seqs, conv1_w, conv1_b, conv2_w, conv2_b, W_w, W_b, amask);
    raw_kernel<<<dim3(LL, BB), 256>>>(tm);
    out_kernel<<<dim3(LL, BB), 256>>>(tm, ln_g, ln_b, out, out_size);
}

// round 14
// speedup vs baseline: 1.4679x; 1.0362x over previous
#include <cuda_runtime.h>
#include <cuda_bf16.h>
#include <float.h>
#include <math.h>

// Problem constants
#define BB 8
#define LL 200
#define DD 256
#define HH 8
#define HS 32
#define HB 64          // H*B
#define KTOP 20
#define NROW 1600      // B*L
#define LNELEM 409600  // B*L*D
#define PADL 216       // compacted list capacity (>=200, mult of 8)

// ---------------- device scratch (no allocs allowed) ----------------
__device__ float g_a[NROW * DD];
__device__ float g_b[NROW * DD];
__device__ float g_w[NROW * DD];
__device__ float g_raw[(size_t)HB * LL * LL];
__device__ unsigned int g_selbits[(size_t)HB * LL * 8]; // topk bitmask, 8 words/row
__device__ unsigned char g_mask[LL * LL];

// ---------------- 3 fused GEMMs + mask convert + selbits zero ------------
// gridDim = (4, 25, 4). z<3: GEMM out = X @ W.T + bias, tile 64x64, 4x4 per
// thread, k-chunk 32, DOUBLE-BUFFERED smem -> one barrier per chunk (8 total).
// z==3: 100 blocks; block 0 converts the attention mask, rest zero selbits.
__global__ void gemm3mz_kernel(const float* __restrict__ X,
                               const float* __restrict__ W0, const float* __restrict__ B0,
                               const float* __restrict__ W1, const float* __restrict__ B1,
                               const float* __restrict__ W2, const float* __restrict__ B2,
                               const void* __restrict__ msrc) {
    if (blockIdx.z == 3) {
        int bi = blockIdx.y * 4 + blockIdx.x;   // 0..99
        int t = threadIdx.x;
        if (bi == 0) {
            __shared__ int flags[4];
            if (t < 4) flags[t] = 0;
            __syncthreads();
            const unsigned char* p = (const unsigned char*)msrc;
            for (int i = t; i < LL * LL; i += 256) {
                if (p[i]) flags[i & 3] = 1;
            }
            __syncthreads();
            int dt;  // 0=u8, 1=i32, 2=f32
            if (flags[1]) dt = 0;
            else if (flags[2] | flags[3]) dt = 2;
            else dt = 1;
            for (int i = t; i < LL * LL; i += 256) {
                unsigned char m;
                if (dt == 0)      m = (p[i] != 0);
                else if (dt == 1) m = (((const int*)msrc)[i] != 0);
                else              m = (((const float*)msrc)[i] != 0.0f);
                g_mask[i] = m;
            }
        } else {
            for (int i = (bi - 1) * 256 + t; i < HB * LL * 8; i += 99 * 256)
                g_selbits[i] = 0u;
        }
        return;
    }

    const float* W; const float* Bv; float* O;
    if (blockIdx.z == 0)      { W = W0; Bv = B0; O = g_a; }
    else if (blockIdx.z == 1) { W = W1; Bv = B1; O = g_b; }
    else                      { W = W2; Bv = B2; O = g_w; }

    __shared__ float As[2][32][68];   // [buf][k][m-row]
    __shared__ float Bs[2][32][68];   // [buf][k][n-row]
    int i0 = blockIdx.y * 64;
    int o0 = blockIdx.x * 64;
    int t = threadIdx.x;
    int tx = t & 15, ty = t >> 4;

    // loader mapping: thread t -> row lr (0..63), 8 consecutive k at lkb
    int lr = t >> 2;
    int lkb = (t & 3) * 8;

    const float* xsrc = &X[(size_t)(i0 + lr) * DD + lkb];
    const float* wsrc = &W[(size_t)(o0 + lr) * DD + lkb];

    float4 xa0 = *(const float4*)(xsrc + 0);
    float4 xa1 = *(const float4*)(xsrc + 4);
    float4 wa0 = *(const float4*)(wsrc + 0);
    float4 wa1 = *(const float4*)(wsrc + 4);

    float acc[4][4];
#pragma unroll
    for (int i = 0; i < 4; i++)
#pragma unroll
        for (int j = 0; j < 4; j++) acc[i][j] = 0.f;

    int buf = 0;
    for (int k0 = 0; k0 < DD; k0 += 32) {
        // store prefetched chunk into buffer `buf` (transposed [k][row])
        As[buf][lkb + 0][lr] = xa0.x; As[buf][lkb + 1][lr] = xa0.y;
        As[buf][lkb + 2][lr] = xa0.z; As[buf][lkb + 3][lr] = xa0.w;
        As[buf][lkb + 4][lr] = xa1.x; As[buf][lkb + 5][lr] = xa1.y;
        As[buf][lkb + 6][lr] = xa1.z; As[buf][lkb + 7][lr] = xa1.w;
        Bs[buf][lkb + 0][lr] = wa0.x; Bs[buf][lkb + 1][lr] = wa0.y;
        Bs[buf][lkb + 2][lr] = wa0.z; Bs[buf][lkb + 3][lr] = wa0.w;
        Bs[buf][lkb + 4][lr] = wa1.x; Bs[buf][lkb + 5][lr] = wa1.y;
        Bs[buf][lkb + 6][lr] = wa1.z; Bs[buf][lkb + 7][lr] = wa1.w;
        __syncthreads();
        if (k0 + 32 < DD) {   // prefetch next chunk while computing this one
            xa0 = *(const float4*)(xsrc + k0 + 32);
            xa1 = *(const float4*)(xsrc + k0 + 36);
            wa0 = *(const float4*)(wsrc + k0 + 32);
            wa1 = *(const float4*)(wsrc + k0 + 36);
        }
#pragma unroll
        for (int kk = 0; kk < 32; kk++) {
            float4 a4 = *(const float4*)&As[buf][kk][ty * 4];
            float4 b4 = *(const float4*)&Bs[buf][kk][tx * 4];
            float am[4] = {a4.x, a4.y, a4.z, a4.w};
            float bn[4] = {b4.x, b4.y, b4.z, b4.w};
#pragma unroll
            for (int mi = 0; mi < 4; mi++)
#pragma unroll
                for (int ni = 0; ni < 4; ni++) acc[mi][ni] += am[mi] * bn[ni];
        }
        buf ^= 1;
    }
#pragma unroll
    for (int mi = 0; mi < 4; mi++) {
#pragma unroll
        for (int ni = 0; ni < 4; ni++) {
            int oo = o0 + tx * 4 + ni;
            O[(size_t)(i0 + ty * 4 + mi) * DD + oo] = acc[mi][ni] + Bv[oo];
        }
    }
}

// ---------------- Pass 1: 4-lanes-per-k geometry + fused top-K -----------
// Block = (q, b), warp h = head h. ksub = lane/4 covers 8 k per iteration;
// j4 = lane%4 owns 8 floats of the head dim. 4 SHFL per 8 k.
__global__ void raw_kernel(const float* __restrict__ tm) {
    int q = blockIdx.x, b = blockIdx.y;
    int t = threadIdx.x, h = t >> 5, lane = t & 31;
    int ksub = lane >> 2, j4 = lane & 3;
    __shared__ float s_row[8][LL];

    const float* arow = g_a + (size_t)(b * LL + q) * DD + h * HS + j4 * 8;
    float4 af0 = *(const float4*)(arow + 0);
    float4 af1 = *(const float4*)(arow + 4);
    float s = af0.x*af0.x + af0.y*af0.y + af0.z*af0.z + af0.w*af0.w
            + af1.x*af1.x + af1.y*af1.y + af1.z*af1.z + af1.w*af1.w;
    s += __shfl_xor_sync(0xffffffffu, s, 1);
    s += __shfl_xor_sync(0xffffffffu, s, 2);
    float a2 = sqrtf(s);

    const float* tibase = tm + (size_t)(b * LL + q) * LL * DD + h * HS + j4 * 8;
    const float* bbase  = g_b + (size_t)b * LL * DD + h * HS + j4 * 8;
    int hb = h * BB + b;
    size_t rowbase = (size_t)(hb * LL + q) * LL;
    const unsigned char* mrow = g_mask + q * LL;

    for (int kb = 0; kb < LL; kb += 8) {
        int k = kb + ksub;
        float4 tv0 = *(const float4*)(tibase + (size_t)k * DD + 0);
        float4 tv1 = *(const float4*)(tibase + (size_t)k * DD + 4);
        float4 bv0 = *(const float4*)(bbase + (size_t)k * DD + 0);
        float4 bv1 = *(const float4*)(bbase + (size_t)k * DD + 4);
        float c0 = bv0.x + tv0.x, c1 = bv0.y + tv0.y;
        float c2 = bv0.z + tv0.z, c3 = bv0.w + tv0.w;
        float c4 = bv1.x + tv1.x, c5 = bv1.y + tv1.y;
        float c6 = bv1.z + tv1.z, c7 = bv1.w + tv1.w;
        float s1 = af0.x*c0 + af0.y*c1 + af0.z*c2 + af0.w*c3
                 + af1.x*c4 + af1.y*c5 + af1.z*c6 + af1.w*c7;
        float s2 = c0*c0 + c1*c1 + c2*c2 + c3*c3
                 + c4*c4 + c5*c5 + c6*c6 + c7*c7;
        s1 += __shfl_xor_sync(0xffffffffu, s1, 1);
        s2 += __shfl_xor_sync(0xffffffffu, s2, 1);
        s1 += __shfl_xor_sync(0xffffffffu, s1, 2);
        s2 += __shfl_xor_sync(0xffffffffu, s2, 2);
        if (j4 == 0) {
            float raw = s1 / (a2 * sqrtf(s2) + 1e-6f);
            if (mrow[k]) raw = 0.f;
            s_row[h][k] = raw;
        }
    }
    __syncwarp();

    for (int i = lane; i < LL; i += 32) g_raw[rowbase + i] = s_row[h][i];

    // ---- fused top-K (jax.lax.top_k tie semantics: ties -> lower index) ----
    float v[7];
#pragma unroll
    for (int i = 0; i < 7; i++) {
        int g = lane + i * 32;
        v[i] = (g < LL) ? s_row[h][g] : -FLT_MAX;
    }
    size_t bits_row = (size_t)(hb * LL + q) * 8;
    for (int it = 0; it < KTOP; it++) {
        float bv = -FLT_MAX;
        int bi = 1 << 30;
#pragma unroll
        for (int i = 0; i < 7; i++) {
            if (v[i] > bv) { bv = v[i]; bi = lane + i * 32; }
        }
#pragma unroll
        for (int off = 16; off; off >>= 1) {
            float ov = __shfl_xor_sync(0xffffffffu, bv, off);
            int   oi = __shfl_xor_sync(0xffffffffu, bi, off);
            if (ov > bv || (ov == bv && oi < bi)) { bv = ov; bi = oi; }
        }
        if (lane == (bi & 31)) v[bi >> 5] = -FLT_MAX;
        if (lane == 0) {
            atomicOr(&g_selbits[bits_row + (bi >> 5)], 1u << (bi & 31));
            atomicOr(&g_selbits[(size_t)(hb * LL + bi) * 8 + (q >> 5)], 1u << (q & 31));
        }
    }
}

// ---------------- Pass 2: compacted + padded gather, LayerNorm -----------
__global__ void out_kernel(const float* __restrict__ tm,
                           const float* __restrict__ gamma,
                           const float* __restrict__ beta,
                           float* __restrict__ out, int out_size) {
    int q = blockIdx.x, b = blockIdx.y;
    int t = threadIdx.x, h = t >> 5, lane = t & 31;
    int hb = h * BB + b;
    __shared__ short s_idx[8][PADL];
    __shared__ float s_val[8][PADL];
    __shared__ float rs[8];

    size_t base = (size_t)(hb * LL + q) * LL;
    size_t bits_row = (size_t)(hb * LL + q) * 8;
    int cnt = 0;
#pragma unroll
    for (int c = 0; c < 7; c++) {
        unsigned m = g_selbits[bits_row + c];    // broadcast load
        int i = c * 32 + lane;
        if ((m >> lane) & 1u) {
            int pos = cnt + __popc(m & ((1u << lane) - 1u));
            s_idx[h][pos] = (short)i;
            s_val[h][pos] = g_raw[base + i];
        }
        cnt += __popc(m);
    }
    __syncwarp();
    int cnt_pad = (cnt + 15) & ~15;
    for (int i = cnt + lane; i < cnt_pad; i += 32) {
        s_idx[h][i] = s_idx[h][0];
        s_val[h][i] = 0.f;
    }
    __syncwarp();

    const float* tirow = tm + (size_t)(b * LL + q) * LL * DD + t;
    const float* wcol  = g_w + (size_t)b * LL * DD + t;
    float acc_o = 0.f, acc_t = 0.f;
    for (int p = 0; p < cnt_pad; p += 16) {
#pragma unroll
        for (int u = 0; u < 16; u++) {
            int k = s_idx[h][p + u];
            float r = s_val[h][p + u];
            acc_o += r * wcol[(size_t)k * DD];
            acc_t += r * tirow[(size_t)k * DD];
        }
    }

    // LayerNorm over the 256 outputs of this block
    float sum = acc_o;
#pragma unroll
    for (int off = 16; off; off >>= 1) sum += __shfl_xor_sync(0xffffffffu, sum, off);
    if (lane == 0) rs[h] = sum;
    __syncthreads();
    float tot = 0.f;
#pragma unroll
    for (int i = 0; i < 8; i++) tot += rs[i];
    float mu = tot * (1.f / 256.f);
    __syncthreads();

    float d = acc_o - mu;
    float sq = d * d;
#pragma unroll
    for (int off = 16; off; off >>= 1) sq += __shfl_xor_sync(0xffffffffu, sq, off);
    if (lane == 0) rs[h] = sq;
    __syncthreads();
    float totq = 0.f;
#pragma unroll
    for (int i = 0; i < 8; i++) totq += rs[i];
    float var = totq * (1.f / 256.f);

    float ln = d * rsqrtf(var + 1e-8f) * gamma[t] + beta[t];
    size_t o = (size_t)(b * LL + q) * DD + t;
    out[o] = ln;
    if (out_size > LNELEM) out[LNELEM + o] = acc_t;
}

// ---------------- launch ----------------
extern "C" void kernel_launch(void* const* d_in, const int* in_sizes, int n_in,
                              void* d_out, int out_size) {
    const float* seqs    = (const float*)d_in[0];
    const void*  amask   = d_in[1];
    const float* tm      = (const float*)d_in[2];
    const float* conv1_w = (const float*)d_in[3];
    const float* conv1_b = (const float*)d_in[4];
    const float* conv2_w = (const float*)d_in[5];
    const float* conv2_b = (const float*)d_in[6];
    const float* W_w     = (const float*)d_in[7];
    const float* W_b     = (const float*)d_in[8];
    const float* ln_g    = (const float*)d_in[9];
    const float* ln_b    = (const float*)d_in[10];
    float* out = (float*)d_out;

    gemm3mz_kernel<<<dim3(4, 25, 4), 256>>>(
        seqs, conv1_w, conv1_b, conv2_w, conv2_b, W_w, W_b, amask);
    raw_kernel<<<dim3(LL, BB), 256>>>(tm);
    out_kernel<<<dim3(LL, BB), 256>>>(tm, ln_g, ln_b, out, out_size);
}